// round 2
// baseline (speedup 1.0000x reference)
#include <cuda_runtime.h>
#include <math.h>

#define B_   8
#define T_   4096
#define D_   128
#define R_   8
#define H2_  256   // 2*D
#define K3_  384   // 3*D
#define MT   64    // rows per tile
#define NTILES (B_*T_/MT)   // 512

struct Sel { float rulew[8]; float alpha; int n_evolve; };
__device__ Sel g_sel;
__device__ float g_buf[2][B_*T_*D_];   // ping-pong cells state (32 MB static scratch)

__device__ __forceinline__ float gelu_exact(float x) {
    return 0.5f * x * (1.0f + erff(x * 0.70710678118654752f));
}

// ---------------------------------------------------------------------------
// Selector: rule softmax, step count, alpha — one small block.
// ---------------------------------------------------------------------------
__global__ void selector_kernel(const float* __restrict__ c,
    const float* __restrict__ rW1, const float* __restrict__ rb1,
    const float* __restrict__ rW2, const float* __restrict__ rb2,
    const float* __restrict__ sW1, const float* __restrict__ sb1,
    const float* __restrict__ sW2, const float* __restrict__ sb2,
    const float* __restrict__ aW1, const float* __restrict__ ab1,
    const float* __restrict__ aW2, const float* __restrict__ ab2)
{
    __shared__ float cs[128];
    __shared__ float hidA[64];
    __shared__ float logA[8];
    __shared__ float hidB[32];
    __shared__ float logB[7];
    __shared__ float hidC[32];
    int t = threadIdx.x;  // 128 threads
    cs[t] = c[t];
    __syncthreads();
    if (t < 64) {
        float s = rb1[t];
        for (int k = 0; k < 128; k++) s = fmaf(cs[k], rW1[k*64 + t], s);
        hidA[t] = gelu_exact(s);
    } else if (t < 96) {
        int j = t - 64;
        float s = sb1[j];
        for (int k = 0; k < 128; k++) s = fmaf(cs[k], sW1[k*32 + j], s);
        hidB[j] = gelu_exact(s);
    } else {
        int j = t - 96;
        float s = ab1[j];
        for (int k = 0; k < 128; k++) s = fmaf(cs[k], aW1[k*32 + j], s);
        hidC[j] = gelu_exact(s);
    }
    __syncthreads();
    if (t < 8) {
        float s = rb2[t];
        for (int k = 0; k < 64; k++) s = fmaf(hidA[k], rW2[k*8 + t], s);
        logA[t] = s;
    } else if (t < 15) {
        int j = t - 8;
        float s = sb2[j];
        for (int k = 0; k < 32; k++) s = fmaf(hidB[k], sW2[k*7 + j], s);
        logB[j] = s;
    }
    __syncthreads();
    if (t == 0) {
        float m = -1e30f;
        for (int i = 0; i < 8; i++) m = fmaxf(m, logA[i]);
        float e[8], den = 0.f;
        for (int i = 0; i < 8; i++) { e[i] = expf(logA[i] - m); den += e[i]; }
        for (int i = 0; i < 8; i++) g_sel.rulew[i] = e[i] / den;
    } else if (t == 1) {
        float m = -1e30f;
        for (int i = 0; i < 7; i++) m = fmaxf(m, logB[i]);
        float e[7], den = 0.f;
        for (int i = 0; i < 7; i++) { e[i] = expf(logB[i] - m); den += e[i]; }
        float n_soft = 0.f;
        for (int i = 0; i < 7; i++) n_soft += (e[i] / den) * (2.0f + (float)i);
        int n = (int)floorf(n_soft + 0.5f);   // python int() on positive value
        n = max(2, min(8, n));
        g_sel.n_evolve = n;
    } else if (t == 2) {
        float s = ab2[0];
        for (int k = 0; k < 32; k++) s = fmaf(hidC[k], aW2[k], s);
        g_sel.alpha = 0.1f + 0.8f / (1.0f + expf(-s));
    }
}

// ---------------------------------------------------------------------------
// Fused evolve step: per 64-row tile:
//   for r in 8 rules:
//     for hc in 4 chunks of 64 h-cols:
//       h = gelu(A[64,384] @ W1[r][:,chunk])  (A read from halo'd cells smem)
//       acc2 += h @ W2[r][chunk,:]
//     out += rulew[r] * tanh(acc2 + b2)
//   dst = alpha*cells + (1-alpha)*out
// ---------------------------------------------------------------------------
// smem layout (floats): s_cells[66][132] | s_w1[32][68] | s_h[64][65] | s_w2[64][128]
#define OFF_W1 (66*132)
#define OFF_H  (OFF_W1 + 32*68)
#define OFF_W2 (OFF_H + 64*65)
#define SMEM_FLOATS (OFF_W2 + 64*128)

__global__ void __launch_bounds__(256, 2) evolve_kernel(
    const float* __restrict__ src_in,
    const float* __restrict__ W1, const float* __restrict__ b1,
    const float* __restrict__ W2, const float* __restrict__ b2, int iter)
{
    if (iter >= g_sel.n_evolve) return;
    const float* __restrict__ src = (iter == 0) ? src_in : g_buf[iter & 1];
    float* __restrict__ dst = g_buf[(iter + 1) & 1];

    extern __shared__ float smem[];
    float* s_cells = smem;            // [66][132] halo'd cells tile
    float* s_w1    = smem + OFF_W1;   // [32][68]  W1 k-panel
    float* s_h     = smem + OFF_H;    // [64][65]  gelu'd h chunk
    float* s_w2    = smem + OFF_W2;   // [64][128] W2 chunk

    const int tid = threadIdx.x;
    const int mt  = blockIdx.x;
    const int b   = mt >> 6;
    const int t0  = (mt & 63) << 6;

    // Load 66-row cells tile (with wraparound halo within this batch)
    for (int idx = tid; idx < 66*128; idx += 256) {
        int i = idx >> 7, c = idx & 127;
        int tt = (t0 - 1 + i + T_) & (T_ - 1);
        s_cells[i*132 + c] = src[(b*T_ + tt)*D_ + c];
    }
    __syncthreads();

    const float alpha = g_sel.alpha;
    const float beta  = 1.0f - alpha;
    const int tr = tid >> 4;   // 0..15 -> 4 rows each
    const int tc = tid & 15;   // 0..15 -> cols

    float out_acc[4][8];
    #pragma unroll
    for (int i = 0; i < 4; i++)
        #pragma unroll
        for (int j = 0; j < 8; j++) out_acc[i][j] = 0.f;

    for (int r = 0; r < R_; r++) {
        const float rw = g_sel.rulew[r];
        float acc2[4][8];
        #pragma unroll
        for (int i = 0; i < 4; i++)
            #pragma unroll
            for (int j = 0; j < 8; j++) acc2[i][j] = b2[r*D_ + tc*8 + j];

        for (int hc = 0; hc < 4; hc++) {
            // ---- GEMM1: h_chunk[64][64] ----
            float hacc[4][4];
            #pragma unroll
            for (int i = 0; i < 4; i++)
                #pragma unroll
                for (int j = 0; j < 4; j++)
                    hacc[i][j] = b1[r*H2_ + hc*64 + tc*4 + j];

            for (int kb = 0; kb < K3_; kb += 32) {
                __syncthreads();   // prior readers of s_w1 (and prev chunk's s_h/s_w2) done
                {   // stage W1 panel [32 rows x 64 cols] -> s_w1
                    int f4 = tid;
                    #pragma unroll
                    for (int p = 0; p < 2; p++, f4 += 256) {
                        int row = f4 >> 4, c4 = f4 & 15;
                        float4 v = *(const float4*)&W1[(size_t)(r*K3_ + kb + row)*H2_ + hc*64 + c4*4];
                        *(float4*)&s_w1[row*68 + c4*4] = v;
                    }
                }
                __syncthreads();
                const int p    = kb >> 7;
                const int drow = (p == 0) ? 0 : ((p == 1) ? -1 : 1);
                const int kc   = kb & 127;
                const float* arow0 = &s_cells[(tr*4 + 1 + drow)*132 + kc];
                #pragma unroll 8
                for (int kk = 0; kk < 32; kk++) {
                    float4 bv = *(const float4*)&s_w1[kk*68 + tc*4];
                    float bb[4] = {bv.x, bv.y, bv.z, bv.w};
                    #pragma unroll
                    for (int i = 0; i < 4; i++) {
                        float a = arow0[i*132 + kk];
                        #pragma unroll
                        for (int j = 0; j < 4; j++)
                            hacc[i][j] = fmaf(a, bb[j], hacc[i][j]);
                    }
                }
            }
            // gelu -> s_h (prev readers of s_h finished before first panel sync above)
            #pragma unroll
            for (int i = 0; i < 4; i++)
                #pragma unroll
                for (int j = 0; j < 4; j++)
                    s_h[(tr*4 + i)*65 + tc*4 + j] = gelu_exact(hacc[i][j]);
            // stage W2 chunk [64][128]
            {
                int f4 = tid;
                #pragma unroll
                for (int p2 = 0; p2 < 8; p2++, f4 += 256) {
                    int row = f4 >> 5, c4 = f4 & 31;
                    *(float4*)&s_w2[row*128 + c4*4] =
                        *(const float4*)&W2[(size_t)(r*H2_ + hc*64 + row)*D_ + c4*4];
                }
            }
            __syncthreads();
            // ---- GEMM2 accumulate: acc2 += h_chunk @ W2chunk ----
            const float* hrow0 = &s_h[(tr*4)*65];
            #pragma unroll 8
            for (int k = 0; k < 64; k++) {
                float4 b0  = *(const float4*)&s_w2[k*128 + tc*8];
                float4 b1v = *(const float4*)&s_w2[k*128 + tc*8 + 4];
                float bb[8] = {b0.x, b0.y, b0.z, b0.w, b1v.x, b1v.y, b1v.z, b1v.w};
                #pragma unroll
                for (int i = 0; i < 4; i++) {
                    float a = hrow0[i*65 + k];
                    #pragma unroll
                    for (int j = 0; j < 8; j++)
                        acc2[i][j] = fmaf(a, bb[j], acc2[i][j]);
                }
            }
        }
        // weighted tanh combine
        #pragma unroll
        for (int i = 0; i < 4; i++)
            #pragma unroll
            for (int j = 0; j < 8; j++)
                out_acc[i][j] = fmaf(rw, tanhf(acc2[i][j]), out_acc[i][j]);
    }

    // final blend + store
    #pragma unroll
    for (int i = 0; i < 4; i++) {
        int m = tr*4 + i;
        size_t grow = (size_t)(b*T_ + t0 + m)*D_ + tc*8;
        float4 o0, o1;
        float* cell = &s_cells[(m + 1)*132 + tc*8];
        o0.x = alpha*cell[0] + beta*out_acc[i][0];
        o0.y = alpha*cell[1] + beta*out_acc[i][1];
        o0.z = alpha*cell[2] + beta*out_acc[i][2];
        o0.w = alpha*cell[3] + beta*out_acc[i][3];
        o1.x = alpha*cell[4] + beta*out_acc[i][4];
        o1.y = alpha*cell[5] + beta*out_acc[i][5];
        o1.z = alpha*cell[6] + beta*out_acc[i][6];
        o1.w = alpha*cell[7] + beta*out_acc[i][7];
        *(float4*)&dst[grow]     = o0;
        *(float4*)&dst[grow + 4] = o1;
    }
}

// ---------------------------------------------------------------------------
// Final LayerNorm: one warp per row; picks ping-pong buffer by n_evolve parity.
// ---------------------------------------------------------------------------
__global__ void ln_kernel(const float* __restrict__ g, const float* __restrict__ bt,
                          float* __restrict__ out)
{
    const int warp = threadIdx.x >> 5, lane = threadIdx.x & 31;
    const int row  = blockIdx.x * 8 + warp;
    const float* __restrict__ src = g_buf[g_sel.n_evolve & 1];
    float4 v = *(const float4*)&src[(size_t)row*128 + lane*4];
    float s  = v.x + v.y + v.z + v.w;
    float sq = v.x*v.x + v.y*v.y + v.z*v.z + v.w*v.w;
    #pragma unroll
    for (int o = 16; o; o >>= 1) {
        s  += __shfl_xor_sync(0xffffffffu, s,  o);
        sq += __shfl_xor_sync(0xffffffffu, sq, o);
    }
    float mu  = s * (1.0f/128.0f);
    float var = sq * (1.0f/128.0f) - mu*mu;
    float rs  = rsqrtf(var + 1e-5f);
    float4 gv = *(const float4*)&g[lane*4];
    float4 bv = *(const float4*)&bt[lane*4];
    float4 o4;
    o4.x = (v.x - mu)*rs*gv.x + bv.x;
    o4.y = (v.y - mu)*rs*gv.y + bv.y;
    o4.z = (v.z - mu)*rs*gv.z + bv.z;
    o4.w = (v.w - mu)*rs*gv.w + bv.w;
    *(float4*)&out[(size_t)row*128 + lane*4] = o4;
}

// ---------------------------------------------------------------------------
extern "C" void kernel_launch(void* const* d_in, const int* in_sizes, int n_in,
                              void* d_out, int out_size)
{
    const float* cells = (const float*)d_in[0];
    const float* c_st  = (const float*)d_in[1];
    const float* W1    = (const float*)d_in[2];
    const float* b1    = (const float*)d_in[3];
    const float* W2    = (const float*)d_in[4];
    const float* b2    = (const float*)d_in[5];
    const float* rW1   = (const float*)d_in[6];
    const float* rb1   = (const float*)d_in[7];
    const float* rW2   = (const float*)d_in[8];
    const float* rb2   = (const float*)d_in[9];
    const float* sW1   = (const float*)d_in[10];
    const float* sb1   = (const float*)d_in[11];
    const float* sW2   = (const float*)d_in[12];
    const float* sb2   = (const float*)d_in[13];
    const float* aW1   = (const float*)d_in[14];
    const float* ab1   = (const float*)d_in[15];
    const float* aW2   = (const float*)d_in[16];
    const float* ab2   = (const float*)d_in[17];
    const float* lng   = (const float*)d_in[18];
    const float* lnb   = (const float*)d_in[19];
    float* out = (float*)d_out;

    const size_t smem_bytes = SMEM_FLOATS * sizeof(float);   // ~92.9 KB
    cudaFuncSetAttribute(evolve_kernel,
                         cudaFuncAttributeMaxDynamicSharedMemorySize, (int)smem_bytes);

    selector_kernel<<<1, 128>>>(c_st, rW1, rb1, rW2, rb2,
                                sW1, sb1, sW2, sb2, aW1, ab1, aW2, ab2);
    for (int i = 0; i < 8; i++)
        evolve_kernel<<<NTILES, 256, smem_bytes>>>(cells, W1, b1, W2, b2, i);
    ln_kernel<<<B_*T_/8, 256>>>(lng, lnb, out);
}

// round 5
// speedup vs baseline: 2.4337x; 2.4337x over previous
#include <cuda_runtime.h>
#include <cuda_bf16.h>
#include <stdint.h>
#include <math.h>

#define B_ 8
#define T_ 4096

// smem layout (bytes)
#define OFF_CH 0          // cells hi: 130 rows x 272B
#define OFF_CL 35360      // cells lo
#define OFF_HH 70720      // H hi: 128 x 144B
#define OFF_HL 89152      // H lo
#define OFF_W1 107584     // 2 bufs x (hi 5120 + lo 5120)
#define OFF_W2 128064     // 2 bufs x (hi 10240 + lo 10240)
#define SMEM_BYTES 169024

struct Sel { float rulew[8]; float alpha; int n_evolve; };
__device__ Sel g_sel;
__device__ float g_buf[2][B_*T_*128];          // ping-pong state
__device__ __nv_bfloat16 g_w1h[8*256*384];     // [r][n=256][k=384] hi
__device__ __nv_bfloat16 g_w1l[8*256*384];     // lo
__device__ __nv_bfloat16 g_w2h[8*128*256];     // [r][n=128][k=256] hi
__device__ __nv_bfloat16 g_w2l[8*128*256];     // lo

__device__ __forceinline__ float gelu_exact(float x){
    return 0.5f*x*(1.0f+erff(x*0.70710678118654752f));
}
__device__ __forceinline__ uint32_t smem_u32(const void* p){
    uint32_t a;
    asm("{ .reg .u64 t; cvta.to.shared.u64 t, %1; cvt.u32.u64 %0, t; }" : "=r"(a) : "l"(p));
    return a;
}
__device__ __forceinline__ void ldsm4(uint32_t* r, uint32_t addr){
    asm volatile("ldmatrix.sync.aligned.m8n8.x4.shared.b16 {%0,%1,%2,%3}, [%4];"
        : "=r"(r[0]),"=r"(r[1]),"=r"(r[2]),"=r"(r[3]) : "r"(addr));
}
__device__ __forceinline__ void mma16816(float* c, const uint32_t* a, uint32_t b0, uint32_t b1){
    asm volatile("mma.sync.aligned.m16n8k16.row.col.f32.bf16.bf16.f32 "
        "{%0,%1,%2,%3}, {%4,%5,%6,%7}, {%8,%9}, {%0,%1,%2,%3};"
        : "+f"(c[0]),"+f"(c[1]),"+f"(c[2]),"+f"(c[3])
        : "r"(a[0]),"r"(a[1]),"r"(a[2]),"r"(a[3]), "r"(b0),"r"(b1));
}
__device__ __forceinline__ uint32_t pack_bf2(float a, float b){
    __nv_bfloat162 t; t.x = __float2bfloat16_rn(a); t.y = __float2bfloat16_rn(b);
    return *(uint32_t*)&t;
}

// ---------------------------------------------------------------------------
// Weight prep: transpose + fp32 -> bf16 hi/lo split
// ---------------------------------------------------------------------------
__global__ void prep_w1(const float* __restrict__ W1){
    int idx = blockIdx.x*256 + threadIdx.x;        // 786432
    int r = idx / 98304, rem = idx - r*98304;
    int k = rem >> 8, n = rem & 255;
    float v = W1[idx];
    __nv_bfloat16 hi = __float2bfloat16_rn(v);
    size_t o = (size_t)(r*256 + n)*384 + k;
    g_w1h[o] = hi;
    g_w1l[o] = __float2bfloat16_rn(v - __bfloat162float(hi));
}
__global__ void prep_w2(const float* __restrict__ W2){
    int idx = blockIdx.x*256 + threadIdx.x;        // 262144
    int r = idx >> 15, rem = idx & 32767;
    int h = rem >> 7, n = rem & 127;
    float v = W2[idx];
    __nv_bfloat16 hi = __float2bfloat16_rn(v);
    size_t o = (size_t)(r*128 + n)*256 + h;
    g_w2h[o] = hi;
    g_w2l[o] = __float2bfloat16_rn(v - __bfloat162float(hi));
}

// ---------------------------------------------------------------------------
// Selector
// ---------------------------------------------------------------------------
__global__ void selector_kernel(const float* __restrict__ c,
    const float* __restrict__ rW1, const float* __restrict__ rb1,
    const float* __restrict__ rW2, const float* __restrict__ rb2,
    const float* __restrict__ sW1, const float* __restrict__ sb1,
    const float* __restrict__ sW2, const float* __restrict__ sb2,
    const float* __restrict__ aW1, const float* __restrict__ ab1,
    const float* __restrict__ aW2, const float* __restrict__ ab2)
{
    __shared__ float cs[128], hidA[64], logA[8], hidB[32], logB[7], hidC[32];
    int t = threadIdx.x;
    cs[t] = c[t];
    __syncthreads();
    if (t < 64) {
        float s = rb1[t];
        for (int k = 0; k < 128; k++) s = fmaf(cs[k], rW1[k*64 + t], s);
        hidA[t] = gelu_exact(s);
    } else if (t < 96) {
        int j = t - 64; float s = sb1[j];
        for (int k = 0; k < 128; k++) s = fmaf(cs[k], sW1[k*32 + j], s);
        hidB[j] = gelu_exact(s);
    } else {
        int j = t - 96; float s = ab1[j];
        for (int k = 0; k < 128; k++) s = fmaf(cs[k], aW1[k*32 + j], s);
        hidC[j] = gelu_exact(s);
    }
    __syncthreads();
    if (t < 8) {
        float s = rb2[t];
        for (int k = 0; k < 64; k++) s = fmaf(hidA[k], rW2[k*8 + t], s);
        logA[t] = s;
    } else if (t < 15) {
        int j = t - 8; float s = sb2[j];
        for (int k = 0; k < 32; k++) s = fmaf(hidB[k], sW2[k*7 + j], s);
        logB[j] = s;
    }
    __syncthreads();
    if (t == 0) {
        float m = -1e30f;
        for (int i = 0; i < 8; i++) m = fmaxf(m, logA[i]);
        float e[8], den = 0.f;
        for (int i = 0; i < 8; i++) { e[i] = expf(logA[i] - m); den += e[i]; }
        for (int i = 0; i < 8; i++) g_sel.rulew[i] = e[i] / den;
    } else if (t == 1) {
        float m = -1e30f;
        for (int i = 0; i < 7; i++) m = fmaxf(m, logB[i]);
        float e[7], den = 0.f;
        for (int i = 0; i < 7; i++) { e[i] = expf(logB[i] - m); den += e[i]; }
        float ns = 0.f;
        for (int i = 0; i < 7; i++) ns += (e[i] / den) * (2.0f + (float)i);
        int n = (int)floorf(ns + 0.5f);
        g_sel.n_evolve = max(2, min(8, n));
    } else if (t == 2) {
        float s = ab2[0];
        for (int k = 0; k < 32; k++) s = fmaf(hidC[k], aW2[k], s);
        g_sel.alpha = 0.1f + 0.8f / (1.0f + expf(-s));
    }
}

// ---------------------------------------------------------------------------
// Staging helpers
// ---------------------------------------------------------------------------
__device__ __forceinline__ void stage_w1(char* sm, int tid, int r, int nh, int kc,
                                         int c, int buf){
    int row = tid >> 2, seg = tid & 3;
    int kbase = (c >> 2)*128 + (c & 3)*32;
    size_t so = (size_t)(r*256 + nh*128 + kc*64 + row)*384 + kbase + seg*8;
    char* d = sm + OFF_W1 + buf*10240 + row*80 + seg*16;
    *(uint4*)d          = *(const uint4*)(g_w1h + so);
    *(uint4*)(d + 5120) = *(const uint4*)(g_w1l + so);
}
__device__ __forceinline__ void stage_w2(char* sm, int tid, int r, int nh, int kc,
                                         int c2, int buf){
    int kbase = nh*128 + kc*64 + c2*32;
    int seg = tid & 3;
    #pragma unroll
    for (int i = 0; i < 2; i++){
        int row = (tid >> 2) + i*64;
        size_t so = (size_t)(r*128 + row)*256 + kbase + seg*8;
        char* d = sm + OFF_W2 + buf*20480 + row*80 + seg*16;
        *(uint4*)d           = *(const uint4*)(g_w2h + so);
        *(uint4*)(d + 10240) = *(const uint4*)(g_w2l + so);
    }
}

// ---------------------------------------------------------------------------
// Fused evolve step, warp-level bf16 MMA with split-3 fp32 emulation
// ---------------------------------------------------------------------------
__global__ void __launch_bounds__(256) evolve_mma(
    const float* __restrict__ src_in,
    const float* __restrict__ b1, const float* __restrict__ b2, int iter)
{
    if (iter >= g_sel.n_evolve) return;
    const float* __restrict__ src = iter ? g_buf[iter & 1] : src_in;
    float* __restrict__ dst = g_buf[(iter + 1) & 1];

    extern __shared__ char sm[];
    const uint32_t sb = smem_u32(sm);
    const int tid = threadIdx.x, w = tid >> 5, lane = tid & 31;
    const int m0 = blockIdx.x*128, bidx = m0 >> 12, t0 = m0 & 4095;

    // ---- load 130-row halo'd cells tile -> bf16 hi/lo planes ----
    for (int idx = tid; idx < 130*32; idx += 256) {
        int row = idx >> 5, q = idx & 31;
        int tt = (t0 - 1 + row) & 4095;
        float4 v = __ldg((const float4*)&src[((size_t)(bidx << 12) + tt)*128 + q*4]);
        __nv_bfloat16 h0 = __float2bfloat16_rn(v.x), h1 = __float2bfloat16_rn(v.y);
        __nv_bfloat16 h2 = __float2bfloat16_rn(v.z), h3 = __float2bfloat16_rn(v.w);
        uint32_t lo01 = pack_bf2(v.x - __bfloat162float(h0), v.y - __bfloat162float(h1));
        uint32_t lo23 = pack_bf2(v.z - __bfloat162float(h2), v.w - __bfloat162float(h3));
        __nv_bfloat162 hp0; hp0.x = h0; hp0.y = h1;
        __nv_bfloat162 hp1; hp1.x = h2; hp1.y = h3;
        *(uint2*)(sm + OFF_CH + row*272 + q*8) = make_uint2(*(uint32_t*)&hp0, *(uint32_t*)&hp1);
        *(uint2*)(sm + OFF_CL + row*272 + q*8) = make_uint2(lo01, lo23);
    }

    const int mrow0 = (w & 3)*32;     // GEMM1/2 m-range
    const int nb1   = (w >> 2)*32;    // GEMM1 n-range (within 64)
    const int nb2   = (w >> 2)*64;    // GEMM2 n-range (within 128)
    const int lrow  = lane & 15;
    const int lsel8 = (lane >> 4) << 3;
    const int nrB   = (lane & 7) + ((lane >> 4) << 3);
    const int selB  = (lane >> 3) & 1;

    float acc2[2][8][4];
    float outa[2][8][4];
    #pragma unroll
    for (int i = 0; i < 2; i++)
        #pragma unroll
        for (int j = 0; j < 8; j++)
            #pragma unroll
            for (int q = 0; q < 4; q++) outa[i][j][q] = 0.f;

    #pragma unroll 1
    for (int r = 0; r < 8; r++) {
        #pragma unroll
        for (int i = 0; i < 2; i++)
            #pragma unroll
            for (int j = 0; j < 8; j++)
                #pragma unroll
                for (int q = 0; q < 4; q++) acc2[i][j][q] = 0.f;

        #pragma unroll 1
        for (int nh = 0; nh < 2; nh++) {
            #pragma unroll 1
            for (int kc = 0; kc < 2; kc++) {
                // ================== GEMM1: C1[128x64] over K=384 ==================
                float C1[2][4][4];
                #pragma unroll
                for (int i = 0; i < 2; i++)
                    #pragma unroll
                    for (int j = 0; j < 4; j++)
                        #pragma unroll
                        for (int q = 0; q < 4; q++) C1[i][j][q] = 0.f;

                __syncthreads();
                stage_w1(sm, tid, r, nh, kc, 0, 0);
                #pragma unroll 1
                for (int c = 0; c < 12; c++) {
                    __syncthreads();
                    if (c + 1 < 12) stage_w1(sm, tid, r, nh, kc, c + 1, (c + 1) & 1);
                    const int p = c >> 2, kcol = (c & 3)*32;
                    const int dp = (p == 0) ? 0 : ((p == 1) ? -1 : 1);
                    const uint32_t aH = sb + OFF_CH
                        + (uint32_t)(mrow0 + 1 + dp + lrow)*272 + (uint32_t)(kcol + lsel8)*2;
                    const uint32_t aL = aH + (OFF_CL - OFF_CH);
                    const uint32_t wb = sb + OFF_W1 + (uint32_t)(c & 1)*10240
                        + (uint32_t)(nb1 + nrB)*80 + (uint32_t)selB*16;
                    #pragma unroll
                    for (int kk = 0; kk < 2; kk++) {
                        uint32_t ah[2][4], al[2][4];
                        ldsm4(ah[0], aH + kk*32);
                        ldsm4(ah[1], aH + 16*272 + kk*32);
                        ldsm4(al[0], aL + kk*32);
                        ldsm4(al[1], aL + 16*272 + kk*32);
                        #pragma unroll
                        for (int g = 0; g < 2; g++) {
                            uint32_t bg[4];
                            ldsm4(bg, wb + (uint32_t)g*16*80 + kk*32);
                            #pragma unroll
                            for (int mt = 0; mt < 2; mt++) {
                                mma16816(C1[mt][g*2+0], ah[mt], bg[0], bg[1]);  // hi*hi
                                mma16816(C1[mt][g*2+1], ah[mt], bg[2], bg[3]);
                                mma16816(C1[mt][g*2+0], al[mt], bg[0], bg[1]);  // lo*hi
                                mma16816(C1[mt][g*2+1], al[mt], bg[2], bg[3]);
                            }
                            ldsm4(bg, wb + 5120 + (uint32_t)g*16*80 + kk*32);
                            #pragma unroll
                            for (int mt = 0; mt < 2; mt++) {
                                mma16816(C1[mt][g*2+0], ah[mt], bg[0], bg[1]);  // hi*lo
                                mma16816(C1[mt][g*2+1], ah[mt], bg[2], bg[3]);
                            }
                        }
                    }
                }
                // ---- GELU + split -> H planes; stage W2 chunk0 ----
                __syncthreads();
                #pragma unroll
                for (int mt = 0; mt < 2; mt++) {
                    #pragma unroll
                    for (int nt = 0; nt < 4; nt++) {
                        int row = mrow0 + mt*16 + (lane >> 2);
                        int colh = nb1 + nt*8 + (lane & 3)*2;
                        float2 bb = *(const float2*)&b1[r*256 + nh*128 + kc*64 + colh];
                        float g0 = gelu_exact(C1[mt][nt][0] + bb.x);
                        float g1 = gelu_exact(C1[mt][nt][1] + bb.y);
                        float g2 = gelu_exact(C1[mt][nt][2] + bb.x);
                        float g3 = gelu_exact(C1[mt][nt][3] + bb.y);
                        __nv_bfloat16 q0 = __float2bfloat16_rn(g0), q1 = __float2bfloat16_rn(g1);
                        __nv_bfloat16 q2 = __float2bfloat16_rn(g2), q3 = __float2bfloat16_rn(g3);
                        __nv_bfloat162 t01; t01.x = q0; t01.y = q1;
                        __nv_bfloat162 t23; t23.x = q2; t23.y = q3;
                        *(uint32_t*)(sm + OFF_HH + row*144 + colh*2)       = *(uint32_t*)&t01;
                        *(uint32_t*)(sm + OFF_HH + (row+8)*144 + colh*2)   = *(uint32_t*)&t23;
                        *(uint32_t*)(sm + OFF_HL + row*144 + colh*2)       =
                            pack_bf2(g0 - __bfloat162float(q0), g1 - __bfloat162float(q1));
                        *(uint32_t*)(sm + OFF_HL + (row+8)*144 + colh*2)   =
                            pack_bf2(g2 - __bfloat162float(q2), g3 - __bfloat162float(q3));
                    }
                }
                stage_w2(sm, tid, r, nh, kc, 0, 0);
                __syncthreads();
                // ================== GEMM2: acc2 += H[128x64] @ W2chunk ==================
                #pragma unroll 1
                for (int c2 = 0; c2 < 2; c2++) {
                    if (c2 == 0) stage_w2(sm, tid, r, nh, kc, 1, 1);
                    const uint32_t hH = sb + OFF_HH
                        + (uint32_t)(mrow0 + lrow)*144 + (uint32_t)(c2*32 + lsel8)*2;
                    const uint32_t hL = hH + (OFF_HL - OFF_HH);
                    const uint32_t wb2 = sb + OFF_W2 + (uint32_t)c2*20480
                        + (uint32_t)nrB*80 + (uint32_t)selB*16;
                    #pragma unroll
                    for (int kk = 0; kk < 2; kk++) {
                        uint32_t ah[2][4], al[2][4];
                        ldsm4(ah[0], hH + kk*32);
                        ldsm4(ah[1], hH + 16*144 + kk*32);
                        ldsm4(al[0], hL + kk*32);
                        ldsm4(al[1], hL + 16*144 + kk*32);
                        #pragma unroll
                        for (int g = 0; g < 4; g++) {
                            uint32_t bg[4];
                            ldsm4(bg, wb2 + (uint32_t)(nb2 + g*16)*80 + kk*32);
                            #pragma unroll
                            for (int mt = 0; mt < 2; mt++) {
                                mma16816(acc2[mt][g*2+0], ah[mt], bg[0], bg[1]);
                                mma16816(acc2[mt][g*2+1], ah[mt], bg[2], bg[3]);
                                mma16816(acc2[mt][g*2+0], al[mt], bg[0], bg[1]);
                                mma16816(acc2[mt][g*2+1], al[mt], bg[2], bg[3]);
                            }
                            ldsm4(bg, wb2 + 10240 + (uint32_t)(nb2 + g*16)*80 + kk*32);
                            #pragma unroll
                            for (int mt = 0; mt < 2; mt++) {
                                mma16816(acc2[mt][g*2+0], ah[mt], bg[0], bg[1]);
                                mma16816(acc2[mt][g*2+1], ah[mt], bg[2], bg[3]);
                            }
                        }
                    }
                    if (c2 == 0) __syncthreads();
                }
            }
        }
        // ---- rule epilogue: outa += rw * tanh(acc2 + b2) ----
        const float rw = g_sel.rulew[r];
        #pragma unroll
        for (int nt = 0; nt < 8; nt++) {
            int col = nb2 + nt*8 + (lane & 3)*2;
            float2 bb = *(const float2*)&b2[r*128 + col];
            #pragma unroll
            for (int mt = 0; mt < 2; mt++) {
                outa[mt][nt][0] = fmaf(rw, tanhf(acc2[mt][nt][0] + bb.x), outa[mt][nt][0]);
                outa[mt][nt][1] = fmaf(rw, tanhf(acc2[mt][nt][1] + bb.y), outa[mt][nt][1]);
                outa[mt][nt][2] = fmaf(rw, tanhf(acc2[mt][nt][2] + bb.x), outa[mt][nt][2]);
                outa[mt][nt][3] = fmaf(rw, tanhf(acc2[mt][nt][3] + bb.y), outa[mt][nt][3]);
            }
        }
    }

    // ---- final blend + store ----
    const float alpha = g_sel.alpha, beta = 1.0f - alpha;
    #pragma unroll
    for (int mt = 0; mt < 2; mt++) {
        #pragma unroll
        for (int nt = 0; nt < 8; nt++) {
            int row = m0 + mrow0 + mt*16 + (lane >> 2);
            int col = nb2 + nt*8 + (lane & 3)*2;
            float2 s0 = *(const float2*)&src[(size_t)row*128 + col];
            float2 s1 = *(const float2*)&src[(size_t)(row+8)*128 + col];
            float2 o0, o1;
            o0.x = alpha*s0.x + beta*outa[mt][nt][0];
            o0.y = alpha*s0.y + beta*outa[mt][nt][1];
            o1.x = alpha*s1.x + beta*outa[mt][nt][2];
            o1.y = alpha*s1.y + beta*outa[mt][nt][3];
            *(float2*)&dst[(size_t)row*128 + col]     = o0;
            *(float2*)&dst[(size_t)(row+8)*128 + col] = o1;
        }
    }
}

// ---------------------------------------------------------------------------
// Final LayerNorm
// ---------------------------------------------------------------------------
__global__ void ln_kernel(const float* __restrict__ g, const float* __restrict__ bt,
                          float* __restrict__ out)
{
    const int warp = threadIdx.x >> 5, lane = threadIdx.x & 31;
    const int row  = blockIdx.x * 8 + warp;
    const float* __restrict__ src = g_buf[g_sel.n_evolve & 1];
    float4 v = *(const float4*)&src[(size_t)row*128 + lane*4];
    float s  = v.x + v.y + v.z + v.w;
    float sq = v.x*v.x + v.y*v.y + v.z*v.z + v.w*v.w;
    #pragma unroll
    for (int o = 16; o; o >>= 1) {
        s  += __shfl_xor_sync(0xffffffffu, s,  o);
        sq += __shfl_xor_sync(0xffffffffu, sq, o);
    }
    float mu  = s * (1.0f/128.0f);
    float var = sq * (1.0f/128.0f) - mu*mu;
    float rs  = rsqrtf(var + 1e-5f);
    float4 gv = *(const float4*)&g[lane*4];
    float4 bv = *(const float4*)&bt[lane*4];
    float4 o4;
    o4.x = (v.x - mu)*rs*gv.x + bv.x;
    o4.y = (v.y - mu)*rs*gv.y + bv.y;
    o4.z = (v.z - mu)*rs*gv.z + bv.z;
    o4.w = (v.w - mu)*rs*gv.w + bv.w;
    *(float4*)&out[(size_t)row*128 + lane*4] = o4;
}

// ---------------------------------------------------------------------------
extern "C" void kernel_launch(void* const* d_in, const int* in_sizes, int n_in,
                              void* d_out, int out_size)
{
    const float* cells = (const float*)d_in[0];
    const float* c_st  = (const float*)d_in[1];
    const float* W1    = (const float*)d_in[2];
    const float* b1    = (const float*)d_in[3];
    const float* W2    = (const float*)d_in[4];
    const float* b2    = (const float*)d_in[5];
    const float* rW1   = (const float*)d_in[6];
    const float* rb1   = (const float*)d_in[7];
    const float* rW2   = (const float*)d_in[8];
    const float* rb2   = (const float*)d_in[9];
    const float* sW1   = (const float*)d_in[10];
    const float* sb1   = (const float*)d_in[11];
    const float* sW2   = (const float*)d_in[12];
    const float* sb2   = (const float*)d_in[13];
    const float* aW1   = (const float*)d_in[14];
    const float* ab1   = (const float*)d_in[15];
    const float* aW2   = (const float*)d_in[16];
    const float* ab2   = (const float*)d_in[17];
    const float* lng   = (const float*)d_in[18];
    const float* lnb   = (const float*)d_in[19];
    float* out = (float*)d_out;

    cudaFuncSetAttribute(evolve_mma, cudaFuncAttributeMaxDynamicSharedMemorySize, SMEM_BYTES);

    prep_w1<<<3072, 256>>>(W1);
    prep_w2<<<1024, 256>>>(W2);
    selector_kernel<<<1, 128>>>(c_st, rW1, rb1, rW2, rb2,
                                sW1, sb1, sW2, sb2, aW1, ab1, aW2, ab2);
    for (int i = 0; i < 8; i++)
        evolve_mma<<<256, 256, SMEM_BYTES>>>(cells, b1, b2, i);
    ln_kernel<<<B_*T_/8, 256>>>(lng, lnb, out);
}

// round 9
// speedup vs baseline: 2.6830x; 1.1024x over previous
#include <cuda_runtime.h>
#include <cuda_bf16.h>
#include <stdint.h>
#include <math.h>

#define B_ 8
#define T_ 4096

// smem layout (bytes)
#define OFF_CH 0          // cells hi: 66 rows x 272B
#define OFF_CL 17952      // cells lo
#define OFF_HH 35904      // H hi: 64 x 144B
#define OFF_HL 45120      // H lo
#define OFF_W  54336      // shared W region: W1 2 bufs x 18432 | W2 hi+lo 36864
#define W1BUF  18432
#define W1LO   9216
#define W2LO   18432
#define SMEM_BYTES 91264

struct Sel { float rulew[8]; float alpha; int n_evolve; };
__device__ Sel g_sel;
__device__ float g_buf[2][B_*T_*128];          // ping-pong state
__device__ __nv_bfloat16 g_w1h[8*256*384];     // [r][n=256][k=384] hi
__device__ __nv_bfloat16 g_w1l[8*256*384];     // lo
__device__ __nv_bfloat16 g_w2h[8*128*256];     // [r][n=128][k=256] hi
__device__ __nv_bfloat16 g_w2l[8*128*256];     // lo

__device__ __forceinline__ float gelu_exact(float x){
    return 0.5f*x*(1.0f+erff(x*0.70710678118654752f));
}
__device__ __forceinline__ uint32_t smem_u32(const void* p){
    uint32_t a;
    asm("{ .reg .u64 t; cvta.to.shared.u64 t, %1; cvt.u32.u64 %0, t; }" : "=r"(a) : "l"(p));
    return a;
}
__device__ __forceinline__ void ldsm4(uint32_t* r, uint32_t addr){
    asm volatile("ldmatrix.sync.aligned.m8n8.x4.shared.b16 {%0,%1,%2,%3}, [%4];"
        : "=r"(r[0]),"=r"(r[1]),"=r"(r[2]),"=r"(r[3]) : "r"(addr));
}
__device__ __forceinline__ void mma16816(float* c, const uint32_t* a, uint32_t b0, uint32_t b1){
    asm volatile("mma.sync.aligned.m16n8k16.row.col.f32.bf16.bf16.f32 "
        "{%0,%1,%2,%3}, {%4,%5,%6,%7}, {%8,%9}, {%0,%1,%2,%3};"
        : "+f"(c[0]),"+f"(c[1]),"+f"(c[2]),"+f"(c[3])
        : "r"(a[0]),"r"(a[1]),"r"(a[2]),"r"(a[3]), "r"(b0),"r"(b1));
}
__device__ __forceinline__ uint32_t pack_bf2(float a, float b){
    __nv_bfloat162 t; t.x = __float2bfloat16_rn(a); t.y = __float2bfloat16_rn(b);
    return *(uint32_t*)&t;
}

// ---------------------------------------------------------------------------
// Weight prep: transpose + fp32 -> bf16 hi/lo split
// ---------------------------------------------------------------------------
__global__ void prep_w1(const float* __restrict__ W1){
    int idx = blockIdx.x*256 + threadIdx.x;        // 786432
    int r = idx / 98304, rem = idx - r*98304;
    int k = rem >> 8, n = rem & 255;
    float v = W1[idx];
    __nv_bfloat16 hi = __float2bfloat16_rn(v);
    size_t o = (size_t)(r*256 + n)*384 + k;
    g_w1h[o] = hi;
    g_w1l[o] = __float2bfloat16_rn(v - __bfloat162float(hi));
}
__global__ void prep_w2(const float* __restrict__ W2){
    int idx = blockIdx.x*256 + threadIdx.x;        // 262144
    int r = idx >> 15, rem = idx & 32767;
    int h = rem >> 7, n = rem & 127;
    float v = W2[idx];
    __nv_bfloat16 hi = __float2bfloat16_rn(v);
    size_t o = (size_t)(r*128 + n)*256 + h;
    g_w2h[o] = hi;
    g_w2l[o] = __float2bfloat16_rn(v - __bfloat162float(hi));
}

// ---------------------------------------------------------------------------
// Selector
// ---------------------------------------------------------------------------
__global__ void selector_kernel(const float* __restrict__ c,
    const float* __restrict__ rW1, const float* __restrict__ rb1,
    const float* __restrict__ rW2, const float* __restrict__ rb2,
    const float* __restrict__ sW1, const float* __restrict__ sb1,
    const float* __restrict__ sW2, const float* __restrict__ sb2,
    const float* __restrict__ aW1, const float* __restrict__ ab1,
    const float* __restrict__ aW2, const float* __restrict__ ab2)
{
    __shared__ float cs[128], hidA[64], logA[8], hidB[32], logB[7], hidC[32];
    int t = threadIdx.x;
    cs[t] = c[t];
    __syncthreads();
    if (t < 64) {
        float s = rb1[t];
        for (int k = 0; k < 128; k++) s = fmaf(cs[k], rW1[k*64 + t], s);
        hidA[t] = gelu_exact(s);
    } else if (t < 96) {
        int j = t - 64; float s = sb1[j];
        for (int k = 0; k < 128; k++) s = fmaf(cs[k], sW1[k*32 + j], s);
        hidB[j] = gelu_exact(s);
    } else {
        int j = t - 96; float s = ab1[j];
        for (int k = 0; k < 128; k++) s = fmaf(cs[k], aW1[k*32 + j], s);
        hidC[j] = gelu_exact(s);
    }
    __syncthreads();
    if (t < 8) {
        float s = rb2[t];
        for (int k = 0; k < 64; k++) s = fmaf(hidA[k], rW2[k*8 + t], s);
        logA[t] = s;
    } else if (t < 15) {
        int j = t - 8; float s = sb2[j];
        for (int k = 0; k < 32; k++) s = fmaf(hidB[k], sW2[k*7 + j], s);
        logB[j] = s;
    }
    __syncthreads();
    if (t == 0) {
        float m = -1e30f;
        for (int i = 0; i < 8; i++) m = fmaxf(m, logA[i]);
        float e[8], den = 0.f;
        for (int i = 0; i < 8; i++) { e[i] = expf(logA[i] - m); den += e[i]; }
        for (int i = 0; i < 8; i++) g_sel.rulew[i] = e[i] / den;
    } else if (t == 1) {
        float m = -1e30f;
        for (int i = 0; i < 7; i++) m = fmaxf(m, logB[i]);
        float e[7], den = 0.f;
        for (int i = 0; i < 7; i++) { e[i] = expf(logB[i] - m); den += e[i]; }
        float ns = 0.f;
        for (int i = 0; i < 7; i++) ns += (e[i] / den) * (2.0f + (float)i);
        int n = (int)floorf(ns + 0.5f);
        g_sel.n_evolve = max(2, min(8, n));
    } else if (t == 2) {
        float s = ab2[0];
        for (int k = 0; k < 32; k++) s = fmaf(hidC[k], aW2[k], s);
        g_sel.alpha = 0.1f + 0.8f / (1.0f + expf(-s));
    }
}

// ---------------------------------------------------------------------------
// Staging helpers
// ---------------------------------------------------------------------------
// W1 chunk c: [64 n-rows x 64 k], hi+lo, stride 144B
__device__ __forceinline__ void stage_w1(char* sm, int tid, int r, int nh, int kc,
                                         int c, int buf){
    int row = tid >> 2, seg = tid & 3;
    int p = c >> 1, kcol = (c & 1)*64;
    size_t so = (size_t)(r*256 + nh*128 + kc*64 + row)*384 + p*128 + kcol + seg*16;
    char* d = sm + OFF_W + buf*W1BUF + row*144 + seg*32;
    *(uint4*)d               = *(const uint4*)(g_w1h + so);
    *(uint4*)(d + 16)        = *(const uint4*)(g_w1h + so + 8);
    *(uint4*)(d + W1LO)      = *(const uint4*)(g_w1l + so);
    *(uint4*)(d + W1LO + 16) = *(const uint4*)(g_w1l + so + 8);
}
// W2 chunk: [128 n-rows x 64 k], hi+lo, stride 144B
__device__ __forceinline__ void stage_w2(char* sm, int tid, int r, int nh, int kc){
    int row = tid >> 1, half = tid & 1;
    size_t so = (size_t)(r*128 + row)*256 + nh*128 + kc*64 + half*32;
    char* d = sm + OFF_W + row*144 + half*64;
    #pragma unroll
    for (int i = 0; i < 4; i++){
        *(uint4*)(d + i*16)        = *(const uint4*)(g_w2h + so + i*8);
        *(uint4*)(d + W2LO + i*16) = *(const uint4*)(g_w2l + so + i*8);
    }
}

// ---------------------------------------------------------------------------
// Fused evolve step, 64-row M-tiles, 2 CTAs/SM
// ---------------------------------------------------------------------------
__global__ void __launch_bounds__(256, 2) evolve_mma(
    const float* __restrict__ src_in,
    const float* __restrict__ b1, const float* __restrict__ b2, int iter)
{
    if (iter >= g_sel.n_evolve) return;
    const float* __restrict__ src = iter ? g_buf[iter & 1] : src_in;
    float* __restrict__ dst = g_buf[(iter + 1) & 1];

    extern __shared__ char sm[];
    const uint32_t sb = smem_u32(sm);
    const int tid = threadIdx.x, w = tid >> 5, lane = tid & 31;
    const int m0 = blockIdx.x*64, bidx = m0 >> 12, t0 = m0 & 4095;

    // ---- load 66-row halo'd cells tile -> bf16 hi/lo planes ----
    for (int idx = tid; idx < 66*32; idx += 256) {
        int row = idx >> 5, q = idx & 31;
        int tt = (t0 - 1 + row) & 4095;
        float4 v = __ldg((const float4*)&src[((size_t)(bidx << 12) + tt)*128 + q*4]);
        __nv_bfloat16 h0 = __float2bfloat16_rn(v.x), h1 = __float2bfloat16_rn(v.y);
        __nv_bfloat16 h2 = __float2bfloat16_rn(v.z), h3 = __float2bfloat16_rn(v.w);
        uint32_t lo01 = pack_bf2(v.x - __bfloat162float(h0), v.y - __bfloat162float(h1));
        uint32_t lo23 = pack_bf2(v.z - __bfloat162float(h2), v.w - __bfloat162float(h3));
        __nv_bfloat162 hp0; hp0.x = h0; hp0.y = h1;
        __nv_bfloat162 hp1; hp1.x = h2; hp1.y = h3;
        *(uint2*)(sm + OFF_CH + row*272 + q*8) = make_uint2(*(uint32_t*)&hp0, *(uint32_t*)&hp1);
        *(uint2*)(sm + OFF_CL + row*272 + q*8) = make_uint2(lo01, lo23);
    }

    const int mw  = w & 3;            // 16-row M slice
    const int nw  = w >> 2;           // N half
    const int nb1 = nw*32;            // GEMM1 cols (of 64)
    const int nb2 = nw*64;            // GEMM2 cols (of 128)
    const int lrow  = lane & 15;
    const int lsel8 = (lane >> 4) << 3;
    const int nrB   = (lane & 7) + ((lane >> 4) << 3);
    const int selB16 = ((lane >> 3) & 1) * 16;

    float acc2[8][4];
    float outa[8][4];
    #pragma unroll
    for (int j = 0; j < 8; j++)
        #pragma unroll
        for (int q = 0; q < 4; q++) outa[j][q] = 0.f;

    #pragma unroll 1
    for (int r = 0; r < 8; r++) {
        #pragma unroll
        for (int j = 0; j < 8; j++)
            #pragma unroll
            for (int q = 0; q < 4; q++) acc2[j][q] = 0.f;

        #pragma unroll 1
        for (int nh = 0; nh < 2; nh++) {
            #pragma unroll 1
            for (int kc = 0; kc < 2; kc++) {
                // ============ GEMM1: C1[64x64] over K=384, k64 chunks ============
                float C1[4][4];
                #pragma unroll
                for (int j = 0; j < 4; j++)
                    #pragma unroll
                    for (int q = 0; q < 4; q++) C1[j][q] = 0.f;

                __syncthreads();                  // W region free
                stage_w1(sm, tid, r, nh, kc, 0, 0);
                #pragma unroll 1
                for (int c = 0; c < 6; c++) {
                    __syncthreads();
                    if (c + 1 < 6) stage_w1(sm, tid, r, nh, kc, c + 1, (c + 1) & 1);
                    const int p = c >> 1, kcol = (c & 1)*64;
                    const int dp = (p == 0) ? 0 : ((p == 1) ? -1 : 1);
                    const uint32_t aH = sb + OFF_CH
                        + (uint32_t)(mw*16 + 1 + dp + lrow)*272 + (uint32_t)(kcol + lsel8)*2;
                    const uint32_t aL = aH + (OFF_CL - OFF_CH);
                    const uint32_t wb = sb + OFF_W + (uint32_t)(c & 1)*W1BUF
                        + (uint32_t)(nb1 + nrB)*144 + (uint32_t)selB16;
                    #pragma unroll
                    for (int kk = 0; kk < 4; kk++) {
                        uint32_t ah[4], al[4];
                        ldsm4(ah, aH + kk*32);
                        ldsm4(al, aL + kk*32);
                        #pragma unroll
                        for (int g = 0; g < 2; g++) {
                            uint32_t bh[4], bl[4];
                            ldsm4(bh, wb + (uint32_t)g*(16*144) + kk*32);
                            ldsm4(bl, wb + W1LO + (uint32_t)g*(16*144) + kk*32);
                            mma16816(C1[g*2+0], ah, bh[0], bh[1]);
                            mma16816(C1[g*2+1], ah, bh[2], bh[3]);
                            mma16816(C1[g*2+0], al, bh[0], bh[1]);
                            mma16816(C1[g*2+1], al, bh[2], bh[3]);
                            mma16816(C1[g*2+0], ah, bl[0], bl[1]);
                            mma16816(C1[g*2+1], ah, bl[2], bl[3]);
                        }
                    }
                }
                __syncthreads();                  // all warps done with W region
                // ---- GELU + split -> H planes; stage W2 ----
                #pragma unroll
                for (int nt = 0; nt < 4; nt++) {
                    int row = mw*16 + (lane >> 2);
                    int colh = nb1 + nt*8 + (lane & 3)*2;
                    float2 bb = *(const float2*)&b1[r*256 + nh*128 + kc*64 + colh];
                    float g0 = gelu_exact(C1[nt][0] + bb.x);
                    float g1 = gelu_exact(C1[nt][1] + bb.y);
                    float g2 = gelu_exact(C1[nt][2] + bb.x);
                    float g3 = gelu_exact(C1[nt][3] + bb.y);
                    __nv_bfloat16 q0 = __float2bfloat16_rn(g0), q1 = __float2bfloat16_rn(g1);
                    __nv_bfloat16 q2 = __float2bfloat16_rn(g2), q3 = __float2bfloat16_rn(g3);
                    __nv_bfloat162 t01; t01.x = q0; t01.y = q1;
                    __nv_bfloat162 t23; t23.x = q2; t23.y = q3;
                    *(uint32_t*)(sm + OFF_HH + row*144 + colh*2)     = *(uint32_t*)&t01;
                    *(uint32_t*)(sm + OFF_HH + (row+8)*144 + colh*2) = *(uint32_t*)&t23;
                    *(uint32_t*)(sm + OFF_HL + row*144 + colh*2)     =
                        pack_bf2(g0 - __bfloat162float(q0), g1 - __bfloat162float(q1));
                    *(uint32_t*)(sm + OFF_HL + (row+8)*144 + colh*2) =
                        pack_bf2(g2 - __bfloat162float(q2), g3 - __bfloat162float(q3));
                }
                stage_w2(sm, tid, r, nh, kc);
                __syncthreads();
                // ============ GEMM2: acc2 += H[64x64] @ W2[64x128] ============
                const uint32_t hH = sb + OFF_HH + (uint32_t)(mw*16 + lrow)*144 + (uint32_t)lsel8*2;
                const uint32_t hL = hH + (OFF_HL - OFF_HH);
                const uint32_t wb2 = sb + OFF_W + (uint32_t)(nb2 + nrB)*144 + (uint32_t)selB16;
                #pragma unroll
                for (int kk = 0; kk < 4; kk++) {
                    uint32_t ah[4], al[4];
                    ldsm4(ah, hH + kk*32);
                    ldsm4(al, hL + kk*32);
                    #pragma unroll
                    for (int g = 0; g < 4; g++) {
                        uint32_t bh[4], bl[4];
                        ldsm4(bh, wb2 + (uint32_t)g*(16*144) + kk*32);
                        ldsm4(bl, wb2 + W2LO + (uint32_t)g*(16*144) + kk*32);
                        mma16816(acc2[g*2+0], ah, bh[0], bh[1]);
                        mma16816(acc2[g*2+1], ah, bh[2], bh[3]);
                        mma16816(acc2[g*2+0], al, bh[0], bh[1]);
                        mma16816(acc2[g*2+1], al, bh[2], bh[3]);
                        mma16816(acc2[g*2+0], ah, bl[0], bl[1]);
                        mma16816(acc2[g*2+1], ah, bl[2], bl[3]);
                    }
                }
            }
        }
        // ---- rule epilogue: outa += rw * tanh(acc2 + b2) ----
        const float rw = g_sel.rulew[r];
        #pragma unroll
        for (int nt = 0; nt < 8; nt++) {
            int col = nb2 + nt*8 + (lane & 3)*2;
            float2 bb = *(const float2*)&b2[r*128 + col];
            outa[nt][0] = fmaf(rw, tanhf(acc2[nt][0] + bb.x), outa[nt][0]);
            outa[nt][1] = fmaf(rw, tanhf(acc2[nt][1] + bb.y), outa[nt][1]);
            outa[nt][2] = fmaf(rw, tanhf(acc2[nt][2] + bb.x), outa[nt][2]);
            outa[nt][3] = fmaf(rw, tanhf(acc2[nt][3] + bb.y), outa[nt][3]);
        }
    }

    // ---- final blend + store ----
    const float alpha = g_sel.alpha, beta = 1.0f - alpha;
    #pragma unroll
    for (int nt = 0; nt < 8; nt++) {
        int row = m0 + mw*16 + (lane >> 2);
        int col = nb2 + nt*8 + (lane & 3)*2;
        float2 s0 = *(const float2*)&src[(size_t)row*128 + col];
        float2 s1 = *(const float2*)&src[(size_t)(row+8)*128 + col];
        float2 o0, o1;
        o0.x = alpha*s0.x + beta*outa[nt][0];
        o0.y = alpha*s0.y + beta*outa[nt][1];
        o1.x = alpha*s1.x + beta*outa[nt][2];
        o1.y = alpha*s1.y + beta*outa[nt][3];
        *(float2*)&dst[(size_t)row*128 + col]     = o0;
        *(float2*)&dst[(size_t)(row+8)*128 + col] = o1;
    }
}

// ---------------------------------------------------------------------------
// Final LayerNorm
// ---------------------------------------------------------------------------
__global__ void ln_kernel(const float* __restrict__ g, const float* __restrict__ bt,
                          float* __restrict__ out)
{
    const int warp = threadIdx.x >> 5, lane = threadIdx.x & 31;
    const int row  = blockIdx.x * 8 + warp;
    const float* __restrict__ src = g_buf[g_sel.n_evolve & 1];
    float4 v = *(const float4*)&src[(size_t)row*128 + lane*4];
    float s  = v.x + v.y + v.z + v.w;
    float sq = v.x*v.x + v.y*v.y + v.z*v.z + v.w*v.w;
    #pragma unroll
    for (int o = 16; o; o >>= 1) {
        s  += __shfl_xor_sync(0xffffffffu, s,  o);
        sq += __shfl_xor_sync(0xffffffffu, sq, o);
    }
    float mu  = s * (1.0f/128.0f);
    float var = sq * (1.0f/128.0f) - mu*mu;
    float rs  = rsqrtf(var + 1e-5f);
    float4 gv = *(const float4*)&g[lane*4];
    float4 bv = *(const float4*)&bt[lane*4];
    float4 o4;
    o4.x = (v.x - mu)*rs*gv.x + bv.x;
    o4.y = (v.y - mu)*rs*gv.y + bv.y;
    o4.z = (v.z - mu)*rs*gv.z + bv.z;
    o4.w = (v.w - mu)*rs*gv.w + bv.w;
    *(float4*)&out[(size_t)row*128 + lane*4] = o4;
}

// ---------------------------------------------------------------------------
extern "C" void kernel_launch(void* const* d_in, const int* in_sizes, int n_in,
                              void* d_out, int out_size)
{
    const float* cells = (const float*)d_in[0];
    const float* c_st  = (const float*)d_in[1];
    const float* W1    = (const float*)d_in[2];
    const float* b1    = (const float*)d_in[3];
    const float* W2    = (const float*)d_in[4];
    const float* b2    = (const float*)d_in[5];
    const float* rW1   = (const float*)d_in[6];
    const float* rb1   = (const float*)d_in[7];
    const float* rW2   = (const float*)d_in[8];
    const float* rb2   = (const float*)d_in[9];
    const float* sW1   = (const float*)d_in[10];
    const float* sb1   = (const float*)d_in[11];
    const float* sW2   = (const float*)d_in[12];
    const float* sb2   = (const float*)d_in[13];
    const float* aW1   = (const float*)d_in[14];
    const float* ab1   = (const float*)d_in[15];
    const float* aW2   = (const float*)d_in[16];
    const float* ab2   = (const float*)d_in[17];
    const float* lng   = (const float*)d_in[18];
    const float* lnb   = (const float*)d_in[19];
    float* out = (float*)d_out;

    cudaFuncSetAttribute(evolve_mma, cudaFuncAttributeMaxDynamicSharedMemorySize, SMEM_BYTES);

    prep_w1<<<3072, 256>>>(W1);
    prep_w2<<<1024, 256>>>(W2);
    selector_kernel<<<1, 128>>>(c_st, rW1, rb1, rW2, rb2,
                                sW1, sb1, sW2, sb2, aW1, ab1, aW2, ab2);
    for (int i = 0; i < 8; i++)
        evolve_mma<<<512, 256, SMEM_BYTES>>>(cells, b1, b2, i);
    ln_kernel<<<B_*T_/8, 256>>>(lng, lnb, out);
}